// round 15
// baseline (speedup 1.0000x reference)
#include <cuda_runtime.h>

// Depthwise 3x3 (center tap zero) + residual, NHWC x[32,56,56,256] fp32.
// Model fit over R1..R14: DRAM% ~ bytes-in-flight/SM (R1 24KB->34%,
// R6 53KB->53%, R3/R10 68KB->65%). R15: R10's rotating mod-6 window at
// FLOAT4 granularity -> 12 outstanding LDG.128 (512B/warp-load) x 16 warps
// ~= 98KB in flight (+44%). Window 72 regs + taps 32 + addr ~115, capped
// at 128 via __launch_bounds__(128,4) = exactly full RF at 16 warps/SM.
// Streaming stores kept from R11.

#define Bn 32
#define Hn 56
#define Wn 56
#define C4 64    // 256 channels / 4 per float4

__device__ __forceinline__ float4 f4fma(float4 k, float4 v, float4 a) {
    a.x = fmaf(k.x, v.x, a.x);
    a.y = fmaf(k.y, v.y, a.y);
    a.z = fmaf(k.z, v.z, a.z);
    a.w = fmaf(k.w, v.w, a.w);
    return a;
}

__global__ __launch_bounds__(128, 4)
void contour_integration_kernel(const float4* __restrict__ x,
                                const float4* __restrict__ k,
                                float4* __restrict__ out)
{
    const int c4 = threadIdx.x;                    // 0..63 channel quad
    const int bh = blockIdx.x * 2 + threadIdx.y;   // 0..B*H-1
    const int h  = bh % Hn;

    const float4 Z = make_float4(0.f, 0.f, 0.f, 0.f);

    // taps (cross-correlation; center k[1][1] excluded)
    float4 k00 = __ldg(&k[0 * C4 + c4]);
    float4 k01 = __ldg(&k[1 * C4 + c4]);
    float4 k02 = __ldg(&k[2 * C4 + c4]);
    float4 k10 = __ldg(&k[3 * C4 + c4]);
    float4 k12 = __ldg(&k[5 * C4 + c4]);
    float4 k20 = __ldg(&k[6 * C4 + c4]);
    float4 k21 = __ldg(&k[7 * C4 + c4]);
    float4 k22 = __ldg(&k[8 * C4 + c4]);

    // boundary rows: zero taps + clamped row pointers -> loads unconditional
    const bool hm = (h > 0);
    const bool hp = (h < Hn - 1);
    if (!hm) { k00 = Z; k01 = Z; k02 = Z; }
    if (!hp) { k20 = Z; k21 = Z; k22 = Z; }

    const int base = bh * Wn * C4 + c4;            // 32-bit safe (6.4M max)
    const float4* __restrict__ row1 = x + base;
    const float4* __restrict__ row0 = hm ? (row1 - Wn * C4) : row1;
    const float4* __restrict__ row2 = hp ? (row1 + Wn * C4) : row1;
    float4* __restrict__ orow = out + base;

    // rotating window: slot(col) = (col + 1) % 6, cols w-1 .. w+4
    float4 win[3][6];

    // prologue: col -1 = Z (slot 0), cols 0..4 -> slots 1..5
    win[0][0] = Z; win[1][0] = Z; win[2][0] = Z;
    #pragma unroll
    for (int p = 1; p <= 5; ++p) {
        const int wc = (p - 1) * C4;
        win[0][p] = __ldg(&row0[wc]);
        win[1][p] = __ldg(&row1[wc]);
        win[2][p] = __ldg(&row2[wc]);
    }

    #pragma unroll
    for (int w = 0; w < Wn; ++w) {
        const int s0 = w % 6;          // col w-1
        const int s1 = (w + 1) % 6;    // col w
        const int s2 = (w + 2) % 6;    // col w+1

        float4 acc = win[1][s1];       // residual (center x)
        acc = f4fma(k00, win[0][s0], acc);
        acc = f4fma(k01, win[0][s1], acc);
        acc = f4fma(k02, win[0][s2], acc);
        acc = f4fma(k10, win[1][s0], acc);
        acc = f4fma(k12, win[1][s2], acc);
        acc = f4fma(k20, win[2][s0], acc);
        acc = f4fma(k21, win[2][s1], acc);
        acc = f4fma(k22, win[2][s2], acc);
        __stcs(&orow[w * C4], acc);    // streaming store: evict-first in L2

        // slot s0 is now free: refill with column w+5 (first used at w+4)
        if (w < Wn - 5) {                          // compile-time (unrolled)
            const int wc = (w + 5) * C4;
            win[0][s0] = __ldg(&row0[wc]);
            win[1][s0] = __ldg(&row1[wc]);
            win[2][s0] = __ldg(&row2[wc]);
        } else if (w == Wn - 5) {
            // phantom col 56 (right edge) must read as zero at w = 55
            win[0][s0] = Z; win[1][s0] = Z; win[2][s0] = Z;
        }
    }
}

extern "C" void kernel_launch(void* const* d_in, const int* in_sizes, int n_in,
                              void* d_out, int out_size)
{
    const float4* x = (const float4*)d_in[0];   // [32,56,56,256] fp32
    const float4* k = (const float4*)d_in[1];   // [3,3,256] fp32
    float4* out = (float4*)d_out;

    dim3 block(C4, 2);          // 128 threads: two full rows per block
    dim3 grid(Bn * Hn / 2);     // 896 blocks
    contour_integration_kernel<<<grid, block>>>(x, k, out);
}

// round 16
// speedup vs baseline: 1.0985x; 1.0985x over previous
#include <cuda_runtime.h>
#include <cstdint>

// Depthwise 3x3 (center tap zero) + residual, NHWC x[32,56,56,256] fp32.
// R1..R15 lesson: register sliding windows couple prefetch depth to register
// count -> occupancy/latency tradeoff plateaus at 37us / DRAM 65%.
// R16: cp.async (LDGSTS) SMEM staging decouples them. Block = (b, channel-
// eighth, 8-row strip); ring of 6 row slots (43KB static smem); row r+4
// staged while row r computes (wait_group 2 = ~2 row-times of cover).
// Compute reads SMEM (29cyc) with a tiny mod-3 register window -> ~65 regs
// AND 4 CTAs/SM (28 warps). Phantom rows staged as zeros = SAME padding.

#define Bn 32
#define Hn 56
#define Wn 56
#define STRIP 8
#define SLOTS 6
#define C2R 16                      // float2 lanes per w (32 channels)
#define SLOT_BYTES (Wn * C2R * 8)   // 7168
#define THREADS 224

__device__ __forceinline__ float2 f2fma(float2 k, float2 v, float2 a) {
    a.x = fmaf(k.x, v.x, a.x);
    a.y = fmaf(k.y, v.y, a.y);
    return a;
}

__global__ __launch_bounds__(THREADS, 4)
void contour_integration_kernel(const float4* __restrict__ x,
                                const float2* __restrict__ k,
                                float2* __restrict__ out)
{
    __shared__ float2 ring[SLOTS][Wn][C2R];   // 43008 B

    const int tid   = threadIdx.x;
    const int ce    = blockIdx.x;             // 0..7 channel-eighth
    const int strip = blockIdx.y;             // 0..6
    const int b     = blockIdx.z;             // 0..31
    const int h0    = strip * STRIP;

    const int c2 = tid & 15;                  // 0..15 float2 lane in eighth
    const int wl = tid >> 4;                  // 0..13 w-lane (4 outputs each)

    const float2 Z = make_float2(0.f, 0.f);

    // taps (cross-correlation; center k[1][1] excluded). 128 float2 per tap row.
    const int kb = ce * 16 + c2;
    const float2 k00 = __ldg(&k[0 * 128 + kb]);
    const float2 k01 = __ldg(&k[1 * 128 + kb]);
    const float2 k02 = __ldg(&k[2 * 128 + kb]);
    const float2 k10 = __ldg(&k[3 * 128 + kb]);
    const float2 k12 = __ldg(&k[5 * 128 + kb]);
    const float2 k20 = __ldg(&k[6 * 128 + kb]);
    const float2 k21 = __ldg(&k[7 * 128 + kb]);
    const float2 k22 = __ldg(&k[8 * 128 + kb]);

    const uint32_t smem_base = (uint32_t)__cvta_generic_to_shared(&ring[0][0][0]);

    // ---- stage row r into slot (cp.async 2x16B per thread; zeros if phantom)
    auto stage = [&](int r, int slot) {
        if (r >= 0 && r < Hn) {
            const float4* g = x + (((b * Hn + r) * Wn) * 64 + ce * 8);
            #pragma unroll
            for (int i = 0; i < 2; ++i) {
                const int idx = tid + i * THREADS;          // 0..447, exact
                const uint32_t d = smem_base + slot * SLOT_BYTES + idx * 16;
                const float4* src = g + (idx >> 3) * 64 + (idx & 7);
                asm volatile("cp.async.cg.shared.global [%0], [%1], 16;\n"
                             :: "r"(d), "l"(src));
            }
        } else {
            float4* s4 = (float4*)((char*)&ring[0][0][0] + slot * SLOT_BYTES);
            const float4 z4 = make_float4(0.f, 0.f, 0.f, 0.f);
            #pragma unroll
            for (int i = 0; i < 2; ++i)
                s4[tid + i * THREADS] = z4;
        }
        asm volatile("cp.async.commit_group;\n" ::: "memory");
    };

    // prologue: rows h0-1 .. h0+3 into slots 0..4 (one group each)
    #pragma unroll
    for (int m = 0; m < 5; ++m)
        stage(h0 - 1 + m, m);

    const int w0 = wl * 4;

    #pragma unroll 1
    for (int j = 0; j < STRIP; ++j) {
        // rows <= h0+j+1 arrived once <=2 groups pending (in-order completion)
        asm volatile("cp.async.wait_group 2;\n" ::: "memory");
        __syncthreads();

        // stage row h0+4+j into the just-freed slot (rows beyond h0+8 unused:
        // stage only j<=4, but ALWAYS commit to keep the group count uniform)
        if (j <= 4) {
            stage(h0 + 4 + j, (5 + j) % SLOTS);
        } else {
            asm volatile("cp.async.commit_group;\n" ::: "memory");
        }

        // compute output row r from ring slots j, j+1, j+2 (mod 6)
        const int r  = h0 + j;
        const float2* __restrict__ A  = &ring[(j    ) % SLOTS][0][c2];  // r-1
        const float2* __restrict__ Bx = &ring[(j + 1) % SLOTS][0][c2];  // r
        const float2* __restrict__ C  = &ring[(j + 2) % SLOTS][0][c2];  // r+1
        float2* __restrict__ orow = out + (((b * Hn + r) * Wn) * 128 + ce * 16 + c2);

        float2 win[3][3];
        if (wl == 0) {
            win[0][0] = Z; win[1][0] = Z; win[2][0] = Z;
        } else {
            win[0][0] = A [(w0 - 1) * C2R];
            win[1][0] = Bx[(w0 - 1) * C2R];
            win[2][0] = C [(w0 - 1) * C2R];
        }
        win[0][1] = A [w0 * C2R];
        win[1][1] = Bx[w0 * C2R];
        win[2][1] = C [w0 * C2R];

        #pragma unroll
        for (int q = 0; q < 4; ++q) {
            const int w = w0 + q;
            if (w + 1 < Wn) {                    // false only for wl=13,q=3
                win[0][2] = A [(w + 1) * C2R];
                win[1][2] = Bx[(w + 1) * C2R];
                win[2][2] = C [(w + 1) * C2R];
            } else {
                win[0][2] = Z; win[1][2] = Z; win[2][2] = Z;
            }

            float2 acc = win[1][1];              // residual (center x)
            acc = f2fma(k00, win[0][0], acc);
            acc = f2fma(k01, win[0][1], acc);
            acc = f2fma(k02, win[0][2], acc);
            acc = f2fma(k10, win[1][0], acc);
            acc = f2fma(k12, win[1][2], acc);
            acc = f2fma(k20, win[2][0], acc);
            acc = f2fma(k21, win[2][1], acc);
            acc = f2fma(k22, win[2][2], acc);
            __stcs(&orow[w * 128], acc);

            win[0][0] = win[0][1]; win[1][0] = win[1][1]; win[2][0] = win[2][1];
            win[0][1] = win[0][2]; win[1][1] = win[1][2]; win[2][1] = win[2][2];
        }
    }
}

extern "C" void kernel_launch(void* const* d_in, const int* in_sizes, int n_in,
                              void* d_out, int out_size)
{
    const float4* x = (const float4*)d_in[0];   // [32,56,56,256] fp32
    const float2* k = (const float2*)d_in[1];   // [3,3,256] fp32
    float2* out = (float2*)d_out;

    dim3 block(THREADS);
    dim3 grid(8, 7, Bn);        // (channel-eighth, h-strip, batch) = 1792 blocks
    contour_integration_kernel<<<grid, block>>>(x, k, out);
}